// round 14
// baseline (speedup 1.0000x reference)
#include <cuda_runtime.h>
#include <math.h>

#define Bz   64
#define Tt   128
#define TM1  127
#define Vv   10000
#define Ee   300
#define Hh   1024
#define G4   4096
#define MROWS (TM1*Bz)   // 8128
#define GRID_REC 128
#define CH    32
#define NCH   32

typedef unsigned long long ull;

// ---------------- scratch (device globals; no allocs allowed) ----------------
__device__ float g_xw[(size_t)MROWS * G4];     // x@w_ih0 + b0, (t,b,4H)
__device__ float g_h1all[(size_t)MROWS * Hh];  // all h1 states, (t,b,H)
__device__ float g_h0[2][Hh * Bz];             // layer0 h, K-MAJOR [k][b]
__device__ float g_h1[2][Hh * Bz];             // layer1 h, K-MAJOR [k][b]
__device__ float g_rowloss[MROWS];
__device__ unsigned g_barcnt;

// ---------------- f32x2 packed-FMA helpers (sm_100+) ----------------
__device__ __forceinline__ ull pk2(float x, float y) {
    ull r; asm("mov.b64 %0, {%1,%2};" : "=l"(r) : "f"(x), "f"(y)); return r;
}
__device__ __forceinline__ ull fma2(ull a, ull b, ull c) {
    ull d; asm("fma.rn.f32x2 %0, %1, %2, %3;" : "=l"(d) : "l"(a), "l"(b), "l"(c)); return d;
}
__device__ __forceinline__ float2 upk(ull v) {
    float2 f; asm("mov.b64 {%0,%1}, %2;" : "=f"(f.x), "=f"(f.y) : "l"(v)); return f;
}
__device__ __forceinline__ float sigf(float x) { return 1.0f / (1.0f + expf(-x)); }

__device__ __forceinline__ unsigned smem_u32(const void* p) {
    unsigned a;
    asm("{ .reg .u64 t; cvta.to.shared.u64 t, %1; cvt.u32.u64 %0, t; }" : "=r"(a) : "l"(p));
    return a;
}
__device__ __forceinline__ void cp16(unsigned dst, const void* src) {
    asm volatile("cp.async.cg.shared.global [%0], [%1], 16;" :: "r"(dst), "l"(src));
}

// grid-wide epoch barrier (all GRID_REC blocks co-resident: 128 <= #SMs)
__device__ __forceinline__ void gbar(unsigned target) {
    __syncthreads();
    if (threadIdx.x == 0) {
        __threadfence();
        atomicAdd(&g_barcnt, 1u);
        unsigned v;
        do {
            asm volatile("ld.acquire.gpu.u32 %0, [%1];" : "=r"(v) : "l"(&g_barcnt));
        } while (v < target);
    }
    __syncthreads();
}

// ---------------- init states ----------------
__global__ void k_init() {
    int i = blockIdx.x * blockDim.x + threadIdx.x;
    if (i < Bz * Hh) {
        g_h0[0][i] = 0.f; g_h1[0][i] = 0.f;
    }
    if (i == 0) g_barcnt = 0u;
}

// ---------------- K2: xW = gather(emb) @ w_ih0 + b0 ----------------
__global__ __launch_bounds__(256) void k_xw(const int* __restrict__ sent,
                                            const float* __restrict__ wordvec,
                                            const float* __restrict__ wih0,
                                            const float* __restrict__ b0) {
    __shared__ float As[8][128];
    __shared__ float Bs[8][128];
    __shared__ int stok[128];

    int tid = threadIdx.x;
    int n0 = blockIdx.x * 128;
    int m0 = blockIdx.y * 128;

    if (tid < 128) {
        int m = m0 + tid;
        int mc = (m < MROWS) ? m : (MROWS - 1);
        int t = mc >> 6, b = mc & 63;
        stok[tid] = sent[b * Tt + t];
    }
    __syncthreads();

    int tx = tid & 15, ty = tid >> 4;
    ull acc[8][4];
#pragma unroll
    for (int i = 0; i < 8; i++)
#pragma unroll
        for (int j = 0; j < 4; j++) acc[i][j] = 0ULL;

    for (int k0 = 0; k0 < Ee; k0 += 8) {
#pragma unroll
        for (int p = 0; p < 4; p++) {
            int idx = tid + p * 256;
            int r = idx & 127, kk = idx >> 7;
            int k = k0 + kk;
            As[kk][r] = (k < Ee) ? wordvec[(size_t)stok[r] * Ee + k] : 0.f;
            Bs[kk][r] = (k < Ee) ? wih0[(size_t)k * G4 + n0 + r] : 0.f;
        }
        __syncthreads();
#pragma unroll
        for (int kk = 0; kk < 8; kk++) {
            ull bf[4];
#pragma unroll
            for (int j = 0; j < 4; j++) bf[j] = *(const ull*)&Bs[kk][32 * j + 2 * tx];
#pragma unroll
            for (int i = 0; i < 8; i++) {
                float a = As[kk][ty + 16 * i];
                ull a2 = pk2(a, a);
#pragma unroll
                for (int j = 0; j < 4; j++) acc[i][j] = fma2(a2, bf[j], acc[i][j]);
            }
        }
        __syncthreads();
    }

#pragma unroll
    for (int i = 0; i < 8; i++) {
        int m = m0 + ty + 16 * i;
        if (m >= MROWS) continue;
        float* orow = g_xw + (size_t)m * G4 + n0;
#pragma unroll
        for (int j = 0; j < 4; j++) {
            float2 v = upk(acc[i][j]);
            int c = 32 * j + 2 * tx;
            orow[c]     = v.x + b0[n0 + c];
            orow[c + 1] = v.y + b0[n0 + c + 1];
        }
    }
}

// ---------------- K3: persistent recurrence, 3 groups, 4x4 tiles, dup'd w -----
// Phase p: L0(t=p) and L1(t=p-1). Block owns 8 hidden units (32 gate cols).
// 3 groups x 128 thr, each a full-K GEMM:
//   g0: h0[p-1] x whh0   g1: h0[p-1] x wih1   g2: h1[p-2] x whh1
// w stored PRE-DUPLICATED in smem (pair-interleaved SWA/SWB so each thread's
// 2 cols are one contiguous 16B LDS.128, conflict-free). Inner loop per kk:
// 3 LDS.128 + 8 FFMA2 (no MOVs). Register-prefetch double buffer; h K-major.
#define SMEM_REC 125824
__global__ void __launch_bounds__(384) k_rec(const float* __restrict__ whh0,
                                             const float* __restrict__ wih1,
                                             const float* __restrict__ whh1,
                                             const float* __restrict__ b1) {
    extern __shared__ __align__(16) char smem[];
    float (*SH0)[CH][64]   = (float (*)[CH][64])(smem);                // 16384
    float (*SH1)[CH][64]   = (float (*)[CH][64])(smem + 16384);        // 16384
    ull   (*SWA)[2][CH][18] = (ull (*)[2][CH][18])(smem + 32768);      // 27648
    ull   (*SWB)[2][CH][18] = (ull (*)[2][CH][18])(smem + 60416);      // 27648
    float (*SGD)[64][33]   = (float (*)[64][33])(smem + 88064);        // 25344
    float (*SXW)[32]       = (float (*)[32])(smem + 113408);           // 8192
    float *SC0 = (float*)(smem + 121600);                               // 2048
    float *SC1 = (float*)(smem + 123648);                               // 2048
    float *SB1 = (float*)(smem + 125696);                               // 128

    const int tid = threadIdx.x;
    const int g   = tid >> 7;            // group 0..2
    const int f   = tid & 127;
    const int tx  = f & 7, ty = f >> 3;  // compute: cols 4tx..+3 (32), rows 4ty..+3 (64)
    const int j0  = blockIdx.x * 8;

    // w fill map: kk = f>>2, gate q = f&3 -> local cols q*8..q*8+7
    const int kkw = f >> 2, qw = f & 3;
    const float* wsrc = (g == 0) ? whh0 : (g == 1) ? wih1 : whh1;
    // h0 fill (tid<256): 2 float4 each
    const int h0k = tid >> 3, h0p = (tid & 7) * 8;
    // h1 fill (g2): 4 float4 each
    const int h1k = f >> 2, h1p = (f & 3) * 16;

    if (tid < 256) { SC0[tid] = 0.f; SC0[tid + 256] = 0.f; SC1[tid] = 0.f; SC1[tid + 256] = 0.f; }
    if (tid < 32) SB1[tid] = b1[((tid >> 3) << 10) + j0 + (tid & 7)];
    __syncthreads();

    const unsigned sxw_base = smem_u32(&SXW[0][0]);

    float4 ra0, ra1, ra2, ra3, rw0, rw1;

    unsigned tgt = 0;

    for (int p = 0; p < 128; p++) {
        const int cur = p & 1, nxt = cur ^ 1;
        const float* hsrc = (g == 2) ? g_h1[nxt] : g_h0[cur];   // K-major [k][64]

        auto ld_fill = [&](int kb) {
            if (g < 2) {
                const float* s = hsrc + (size_t)(kb + h0k) * 64 + h0p;
                ra0 = __ldcg((const float4*)s);
                ra1 = __ldcg((const float4*)(s + 4));
            } else {
                const float* s = hsrc + (size_t)(kb + h1k) * 64 + h1p;
                ra0 = __ldcg((const float4*)s);
                ra1 = __ldcg((const float4*)(s + 4));
                ra2 = __ldcg((const float4*)(s + 8));
                ra3 = __ldcg((const float4*)(s + 12));
            }
            const float* ws = wsrc + (size_t)(kb + kkw) * G4 + (size_t)qw * Hh + j0;
            rw0 = __ldg((const float4*)ws);
            rw1 = __ldg((const float4*)(ws + 4));
        };
        // local col c = qw*8+u maps: compute-thread tx=c>>2 reads SWA pair
        // (cols 4tx,4tx+1) at ull idx 2tx, SWB pair (4tx+2,4tx+3) at 2tx.
        // So col c -> (c&3)<2 ? SWA[2*(c>>2)+(c&1)] : SWB[2*(c>>2)+(c&1)].
        auto st_fill = [&](int buf) {
            if (g < 2) {
                *(float4*)&SH0[buf][h0k][h0p]     = ra0;
                *(float4*)&SH0[buf][h0k][h0p + 4] = ra1;
            } else {
                *(float4*)&SH1[buf][h1k][h1p]      = ra0;
                *(float4*)&SH1[buf][h1k][h1p + 4]  = ra1;
                *(float4*)&SH1[buf][h1k][h1p + 8]  = ra2;
                *(float4*)&SH1[buf][h1k][h1p + 12] = ra3;
            }
            // cols qw*8+{0..7}: u0,u1->SWA[4qw,4qw+1]; u2,u3->SWB[4qw,4qw+1];
            //                   u4,u5->SWA[4qw+2,4qw+3]; u6,u7->SWB[4qw+2,4qw+3]
            *(ulonglong2*)&SWA[g][buf][kkw][4 * qw] =
                make_ulonglong2(pk2(rw0.x, rw0.x), pk2(rw0.y, rw0.y));
            *(ulonglong2*)&SWB[g][buf][kkw][4 * qw] =
                make_ulonglong2(pk2(rw0.z, rw0.z), pk2(rw0.w, rw0.w));
            *(ulonglong2*)&SWA[g][buf][kkw][4 * qw + 2] =
                make_ulonglong2(pk2(rw1.x, rw1.x), pk2(rw1.y, rw1.y));
            *(ulonglong2*)&SWB[g][buf][kkw][4 * qw + 2] =
                make_ulonglong2(pk2(rw1.z, rw1.z), pk2(rw1.w, rw1.w));
        };
        auto barg = [&]() {
            if (g < 2) asm volatile("bar.sync 1, 256;" ::: "memory");
            else       asm volatile("bar.sync 2, 128;" ::: "memory");
        };

        // xw[t=p] prefetch (64 x 32) via cp.async, tid<256, 2 cp16 each
        if (tid < 256 && p < 127) {
            int b = tid >> 2, q = tid & 3;
            const float* src = g_xw + ((size_t)p * Bz + b) * G4 + (size_t)q * Hh + j0;
            cp16(sxw_base + (unsigned)(b * 32 + q * 8) * 4u, src);
            cp16(sxw_base + (unsigned)(b * 32 + q * 8 + 4) * 4u, src + 4);
            asm volatile("cp.async.commit_group;");
        }

        ull acc[8];
#pragma unroll
        for (int i = 0; i < 8; i++) acc[i] = 0ULL;

        ld_fill(0);
        st_fill(0);
        barg();

        int buf = 0;
        for (int c = 0; c < NCH; c++) {
            if (c < NCH - 1) ld_fill((c + 1) * CH);
            {
                const float* hb = (g < 2) ? &SH0[buf][0][0] : &SH1[buf][0][0];
                const ull* wa = &SWA[g][buf][0][0];
                const ull* wb = &SWB[g][buf][0][0];
#pragma unroll
                for (int kk = 0; kk < CH; kk++) {
                    ulonglong2 hA = *(const ulonglong2*)(hb + kk * 64 + 4 * ty);
                    ulonglong2 wA = *(const ulonglong2*)(wa + kk * 18 + 2 * tx);
                    ulonglong2 wB = *(const ulonglong2*)(wb + kk * 18 + 2 * tx);
                    acc[0] = fma2(hA.x, wA.x, acc[0]);
                    acc[1] = fma2(hA.y, wA.x, acc[1]);
                    acc[2] = fma2(hA.x, wA.y, acc[2]);
                    acc[3] = fma2(hA.y, wA.y, acc[3]);
                    acc[4] = fma2(hA.x, wB.x, acc[4]);
                    acc[5] = fma2(hA.y, wB.x, acc[5]);
                    acc[6] = fma2(hA.x, wB.y, acc[6]);
                    acc[7] = fma2(hA.y, wB.y, acc[7]);
                }
            }
            if (c < NCH - 1) st_fill(buf ^ 1);
            barg();
            buf ^= 1;
        }

        // stage gate partials: rows 4ty..+3, cols 4tx..+3
        {
#pragma unroll
            for (int j = 0; j < 4; j++) {
                float2 v = upk(acc[2 * j]);
                float2 u = upk(acc[2 * j + 1]);
                SGD[g][4 * ty + 0][4 * tx + j] = v.x;
                SGD[g][4 * ty + 1][4 * tx + j] = v.y;
                SGD[g][4 * ty + 2][4 * tx + j] = u.x;
                SGD[g][4 * ty + 3][4 * tx + j] = u.y;
            }
        }
        if (tid < 256 && p < 127) asm volatile("cp.async.wait_group 0;");
        __syncthreads();

        if (g == 0) {
            if (p < 127) {
#pragma unroll
                for (int e = 0; e < 4; e++) {
                    int idx = f + 128 * e;             // 0..511
                    int bb = idx & 63, jj = idx >> 6;  // jj 0..7
                    float iv = SGD[0][bb][jj]      + SXW[bb][jj];
                    float fv = SGD[0][bb][8 + jj]  + SXW[bb][8 + jj];
                    float gv = SGD[0][bb][16 + jj] + SXW[bb][16 + jj];
                    float ov = SGD[0][bb][24 + jj] + SXW[bb][24 + jj];
                    float co = SC0[idx];
                    float cn = sigf(fv) * co + sigf(iv) * tanhf(gv);
                    float hn = sigf(ov) * tanhf(cn);
                    SC0[idx] = cn;
                    g_h0[nxt][(size_t)(j0 + jj) * 64 + bb] = hn;
                }
            }
        } else if (g == 1) {
            if (p > 0) {
                int t = p - 1;
#pragma unroll
                for (int e = 0; e < 4; e++) {
                    int idx = f + 128 * e;
                    int bb = idx & 63, jj = idx >> 6;
                    float iv = SGD[1][bb][jj]      + SGD[2][bb][jj]      + SB1[jj];
                    float fv = SGD[1][bb][8 + jj]  + SGD[2][bb][8 + jj]  + SB1[8 + jj];
                    float gv = SGD[1][bb][16 + jj] + SGD[2][bb][16 + jj] + SB1[16 + jj];
                    float ov = SGD[1][bb][24 + jj] + SGD[2][bb][24 + jj] + SB1[24 + jj];
                    float co = SC1[idx];
                    float cn = sigf(fv) * co + sigf(iv) * tanhf(gv);
                    float hn = sigf(ov) * tanhf(cn);
                    SC1[idx] = cn;
                    g_h1[cur][(size_t)(j0 + jj) * 64 + bb] = hn;
                    g_h1all[((size_t)t * Bz + bb) * Hh + j0 + jj] = hn;
                }
            }
        }

        if (p < 127) { tgt += GRID_REC; gbar(tgt); }
    }
}

// ---------------- K4: logits = h1_all @ w_out + b_out (double-buffered) -------
__global__ __launch_bounds__(256, 2) void k_logits(const float* __restrict__ wout,
                                                   const float* __restrict__ bout,
                                                   float* __restrict__ out) {
    __shared__ __align__(16) float As[2][8][132];
    __shared__ __align__(16) ull   Bd[2][8][128];
    __shared__ int aoff[128];

    int tid = threadIdx.x;
    int n0 = blockIdx.x * 128;
    int m0 = blockIdx.y * 128;

    if (tid < 128) {
        int m = m0 + tid;
        int mc = (m < MROWS) ? m : (MROWS - 1);
        int b = mc / 127, t = mc - b * 127;
        aoff[tid] = t * Bz + b;
    }
    __syncthreads();

    int tx = tid & 31, wy = tid >> 5;
    int ar = tid >> 1, akq = tid & 1;
    int bkk = tid >> 5, bc = (tid & 31) * 4;
    bool bok = (n0 + bc + 3 < Vv);

    ull acc[8][4];
#pragma unroll
    for (int p = 0; p < 8; p++)
#pragma unroll
        for (int j = 0; j < 4; j++) acc[p][j] = 0ULL;

    auto ldA = [&](int k0) -> float4 {
        return __ldg((const float4*)(g_h1all + (size_t)aoff[ar] * Hh + k0 + akq * 4));
    };
    auto ldB = [&](int k0) -> float4 {
        float4 bv = make_float4(0.f, 0.f, 0.f, 0.f);
        if (bok) {
            bv = __ldg((const float4*)(wout + (size_t)(k0 + bkk) * Vv + n0 + bc));
        } else {
            const float* wr = wout + (size_t)(k0 + bkk) * Vv;
            if (n0 + bc + 0 < Vv) bv.x = wr[n0 + bc + 0];
            if (n0 + bc + 1 < Vv) bv.y = wr[n0 + bc + 1];
            if (n0 + bc + 2 < Vv) bv.z = wr[n0 + bc + 2];
            if (n0 + bc + 3 < Vv) bv.w = wr[n0 + bc + 3];
        }
        return bv;
    };
    auto sts = [&](int bf, float4 av, float4 bv) {
        As[bf][akq * 4 + 0][ar] = av.x; As[bf][akq * 4 + 1][ar] = av.y;
        As[bf][akq * 4 + 2][ar] = av.z; As[bf][akq * 4 + 3][ar] = av.w;
        Bd[bf][bkk][bc + 0] = pk2(bv.x, bv.x); Bd[bf][bkk][bc + 1] = pk2(bv.y, bv.y);
        Bd[bf][bkk][bc + 2] = pk2(bv.z, bv.z); Bd[bf][bkk][bc + 3] = pk2(bv.w, bv.w);
    };

    float4 av = ldA(0), bv = ldB(0);
    sts(0, av, bv);
    __syncthreads();
    int buf = 0;

    for (int k0 = 0; k0 < Hh; k0 += 8) {
        bool more = (k0 + 8 < Hh);
        if (more) { av = ldA(k0 + 8); bv = ldB(k0 + 8); }
#pragma unroll
        for (int kk = 0; kk < 8; kk++) {
            ulonglong2 A0 = *(const ulonglong2*)&As[buf][kk][wy * 16 + 0];
            ulonglong2 A1 = *(const ulonglong2*)&As[buf][kk][wy * 16 + 4];
            ulonglong2 A2 = *(const ulonglong2*)&As[buf][kk][wy * 16 + 8];
            ulonglong2 A3 = *(const ulonglong2*)&As[buf][kk][wy * 16 + 12];
            ull hr[8] = {A0.x, A0.y, A1.x, A1.y, A2.x, A2.y, A3.x, A3.y};
#pragma unroll
            for (int j = 0; j < 4; j++) {
                ull w = Bd[buf][kk][tx + 32 * j];
#pragma unroll
                for (int p = 0; p < 8; p++) acc[p][j] = fma2(hr[p], w, acc[p][j]);
            }
        }
        if (more) sts(buf ^ 1, av, bv);
        __syncthreads();
        buf ^= 1;
    }

#pragma unroll
    for (int p = 0; p < 8; p++) {
        int m = m0 + wy * 16 + 2 * p;
#pragma unroll
        for (int j = 0; j < 4; j++) {
            int n = n0 + tx + 32 * j;
            if (n < Vv) {
                float2 v = upk(acc[p][j]);
                float bo = bout[n];
                if (m < MROWS)     out[1 + (size_t)m * Vv + n]       = v.x + bo;
                if (m + 1 < MROWS) out[1 + (size_t)(m + 1) * Vv + n] = v.y + bo;
            }
        }
    }
}

// ---------------- K5: per-row log-softmax at gt; masked by PAD ----------------
__global__ __launch_bounds__(256) void k_rowloss(const float* __restrict__ out,
                                                 const int* __restrict__ sent) {
    __shared__ float red[256];
    int m = blockIdx.x;
    const float* row = out + 1 + (size_t)m * Vv;
    int tid = threadIdx.x;

    float mx = -3.4e38f;
    for (int v = tid; v < Vv; v += 256) mx = fmaxf(mx, row[v]);
    red[tid] = mx; __syncthreads();
    for (int s = 128; s > 0; s >>= 1) {
        if (tid < s) red[tid] = fmaxf(red[tid], red[tid + s]);
        __syncthreads();
    }
    mx = red[0]; __syncthreads();

    float sm = 0.f;
    for (int v = tid; v < Vv; v += 256) sm += expf(row[v] - mx);
    red[tid] = sm; __syncthreads();
    for (int s = 128; s > 0; s >>= 1) {
        if (tid < s) red[tid] += red[tid + s];
        __syncthreads();
    }

    if (tid == 0) {
        int b = m / 127, t = m - b * 127;
        int gt = sent[b * Tt + t + 1];
        float lp = 0.f;
        if (gt != 0) lp = row[gt] - mx - logf(red[0]);
        g_rowloss[m] = lp;
    }
}

// ---------------- K6: deterministic loss reduction ----------------
__global__ void k_loss(const int* __restrict__ length, float* __restrict__ out) {
    __shared__ float sb[64];
    int b = threadIdx.x;
    float a = 0.f;
    for (int t = 0; t < TM1; t++) a += g_rowloss[b * TM1 + t];
    sb[b] = -a / (float)length[b];
    __syncthreads();
    if (b == 0) {
        float s = 0.f;
        for (int i = 0; i < 64; i++) s += sb[i];
        out[0] = s;
    }
}

// ---------------- host ----------------
extern "C" void kernel_launch(void* const* d_in, const int* in_sizes, int n_in,
                              void* d_out, int out_size) {
    const int*   sent    = (const int*)d_in[0];
    const int*   length  = (const int*)d_in[1];
    const float* wordvec = (const float*)d_in[2];
    const float* wih0    = (const float*)d_in[3];
    const float* whh0    = (const float*)d_in[4];
    const float* b0      = (const float*)d_in[5];
    const float* wih1    = (const float*)d_in[6];
    const float* whh1    = (const float*)d_in[7];
    const float* b1      = (const float*)d_in[8];
    const float* wout    = (const float*)d_in[9];
    const float* bout    = (const float*)d_in[10];
    float* out = (float*)d_out;

    static int smem_set = 0;
    if (!smem_set) {
        cudaFuncSetAttribute(k_rec, cudaFuncAttributeMaxDynamicSharedMemorySize, SMEM_REC);
        smem_set = 1;
    }

    k_init<<<256, 256>>>();
    k_xw<<<dim3(G4 / 128, 64), 256>>>(sent, wordvec, wih0, b0);
    k_rec<<<GRID_REC, 384, SMEM_REC>>>(whh0, wih1, whh1, b1);
    k_logits<<<dim3((Vv + 127) / 128, (MROWS + 127) / 128), 256>>>(wout, bout, out);
    k_rowloss<<<MROWS, 256>>>(out, sent);
    k_loss<<<1, 64>>>(length, out);
}